// round 2
// baseline (speedup 1.0000x reference)
#include <cuda_runtime.h>

// Problem constants (fixed by the reference setup)
#define BZ_ 8
#define NF_ 10000
#define D_  16
#define H_  512
#define W_  512
#define HW_ (H_ * W_)
#define NPIX (BZ_ * HW_)     // 2097152, divisible by 128
#define CH_ (D_ + 1)         // 17 output channels
#define TPB 128
#define ROW 13               // padded float4 row per pixel (12 data + 1 pad)

__global__ void __launch_bounds__(TPB)
render_kernel(const float4* __restrict__ attrs,   // [BZ*NF, 12] float4 (3 verts x 16 floats)
              const float*  __restrict__ baryw,   // [BZ, H, W, 3]
              const int*    __restrict__ tri,     // [BZ, H, W]
              float*        __restrict__ out)     // [BZ, 17, H, W]
{
    __shared__ float4 s_attr[TPB * ROW];          // 26624 B
    __shared__ int    s_idx[TPB];

    const int tid = threadIdx.x;
    const int p   = blockIdx.x * TPB + tid;       // my pixel (always in range)

    const int t = tri[p];
    s_idx[tid] = (t < 0) ? 0 : t;                 // clamp bg to face 0 (matches reference)
    __syncthreads();

    // Cooperative gather: TPB*12 float4 loads, consecutive lanes hit
    // consecutive addresses within each pixel's contiguous 192B region.
    #pragma unroll
    for (int k = 0; k < 12; k++) {
        const int j    = k * TPB + tid;
        const int pix  = j / 12;
        const int comp = j - pix * 12;
        const int idx  = s_idx[pix];
        s_attr[pix * ROW + comp] = attrs[(size_t)idx * 12 + comp];
    }
    __syncthreads();

    // Per-pixel blend from shared memory (conflict-free: 52-float stride)
    const int n   = p / HW_;
    const int pix = p - n * HW_;
    float* outp = out + (size_t)n * CH_ * HW_ + pix;

    if (t < 0) {
        #pragma unroll
        for (int d = 0; d < CH_; d++)
            outp[(size_t)d * HW_] = 0.0f;
        return;
    }

    const float w0 = baryw[3 * p + 0];
    const float w1 = baryw[3 * p + 1];
    const float w2 = baryw[3 * p + 2];

    const float4* mine = &s_attr[tid * ROW];

    #pragma unroll
    for (int i = 0; i < 4; i++) {
        const float4 a = mine[i];
        const float4 b = mine[4 + i];
        const float4 c = mine[8 + i];
        float4 r;
        r.x = fmaf(w0, a.x, fmaf(w1, b.x, w2 * c.x));
        r.y = fmaf(w0, a.y, fmaf(w1, b.y, w2 * c.y));
        r.z = fmaf(w0, a.z, fmaf(w1, b.z, w2 * c.z));
        r.w = fmaf(w0, a.w, fmaf(w1, b.w, w2 * c.w));
        outp[(size_t)(4 * i + 0) * HW_] = r.x;
        outp[(size_t)(4 * i + 1) * HW_] = r.y;
        outp[(size_t)(4 * i + 2) * HW_] = r.z;
        outp[(size_t)(4 * i + 3) * HW_] = r.w;
    }
    outp[(size_t)D_ * HW_] = 1.0f;   // visibility channel
}

extern "C" void kernel_launch(void* const* d_in, const int* in_sizes, int n_in,
                              void* d_out, int out_size)
{
    const float4* attrs = (const float4*)d_in[0];
    const float*  baryw = (const float*)d_in[1];
    const int*    tri   = (const int*)d_in[2];
    float*        out   = (float*)d_out;

    render_kernel<<<NPIX / TPB, TPB>>>(attrs, baryw, tri, out);
}

// round 3
// speedup vs baseline: 1.8584x; 1.8584x over previous
#include <cuda_runtime.h>

// Problem constants (fixed by the reference setup)
#define BZ_ 8
#define NF_ 10000
#define D_  16
#define H_  512
#define W_  512
#define HW_ (H_ * W_)        // 262144 = 2^18
#define NPIX (BZ_ * HW_)     // 2097152
#define CH_ (D_ + 1)         // 17 output channels
#define TPB 256
#define PPB (TPB / 4)        // 64 pixels per block

__global__ void __launch_bounds__(TPB)
render_kernel(const float4* __restrict__ attrs,   // [BZ*NF, 12] float4 (3 verts x 16 floats)
              const float*  __restrict__ baryw,   // [BZ, H, W, 3]
              const int*    __restrict__ tri,     // [BZ, H, W]
              float*        __restrict__ out)     // [BZ, 17, H, W]
{
    const int tid = threadIdx.x;
    const int q   = tid & 3;                       // which 4-channel slice I own
    const int p   = blockIdx.x * PPB + (tid >> 2); // my pixel

    const int n   = p >> 18;                       // p / HW_
    const int pix = p & (HW_ - 1);
    float* outp = out + (size_t)n * CH_ * HW_ + pix + (size_t)(4 * q) * HW_;

    const int t = tri[p];

    if (t < 0) {
        // background: extremely rare (P ~ 1/80001); zero my 4 channels + vis
        outp[(size_t)0 * HW_] = 0.0f;
        outp[(size_t)1 * HW_] = 0.0f;
        outp[(size_t)2 * HW_] = 0.0f;
        outp[(size_t)3 * HW_] = 0.0f;
        if (q == 0) outp[(size_t)(D_ - 0) * HW_ + (size_t)(D_ - 4 * q) * 0] = 0.0f; // placeholder, fixed below
        if (q == 0) out[(size_t)n * CH_ * HW_ + (size_t)D_ * HW_ + pix] = 0.0f;
        return;
    }

    const float w0 = baryw[3 * p + 0];
    const float w1 = baryw[3 * p + 1];
    const float w2 = baryw[3 * p + 2];

    // my 3 float4 gathers: 64B-aligned 64B chunks -> 1 L1 line each, warp-wide 8 lines/instr
    const float4* v = attrs + t * 12 + q;
    const float4 a = v[0];
    const float4 b = v[4];
    const float4 c = v[8];

    float4 r;
    r.x = fmaf(w0, a.x, fmaf(w1, b.x, w2 * c.x));
    r.y = fmaf(w0, a.y, fmaf(w1, b.y, w2 * c.y));
    r.z = fmaf(w0, a.z, fmaf(w1, b.z, w2 * c.z));
    r.w = fmaf(w0, a.w, fmaf(w1, b.w, w2 * c.w));

    outp[(size_t)0 * HW_] = r.x;
    outp[(size_t)1 * HW_] = r.y;
    outp[(size_t)2 * HW_] = r.z;
    outp[(size_t)3 * HW_] = r.w;
    if (q == 0)
        out[(size_t)n * CH_ * HW_ + (size_t)D_ * HW_ + pix] = 1.0f;  // visibility
}

extern "C" void kernel_launch(void* const* d_in, const int* in_sizes, int n_in,
                              void* d_out, int out_size)
{
    const float4* attrs = (const float4*)d_in[0];
    const float*  baryw = (const float*)d_in[1];
    const int*    tri   = (const int*)d_in[2];
    float*        out   = (float*)d_out;

    render_kernel<<<NPIX / PPB, TPB>>>(attrs, baryw, tri, out);
}